// round 3
// baseline (speedup 1.0000x reference)
#include <cuda_runtime.h>

#define N_RES 1024
#define C_M   256
#define C_Z   128
#define NUM_BINS 15

// ---------------------------------------------------------------------------
// m layernorm: one warp per row of m [1024, 256]; 2 float4 per lane.
// ---------------------------------------------------------------------------
__global__ void m_ln_kernel(const float* __restrict__ m,
                            const float* __restrict__ w,
                            const float* __restrict__ b,
                            float* __restrict__ out) {
    int gwarp = (blockIdx.x * blockDim.x + threadIdx.x) >> 5;
    int lane  = threadIdx.x & 31;
    if (gwarp >= N_RES) return;

    const float4* mr = (const float4*)(m + (size_t)gwarp * C_M);
    float4 a0 = mr[lane];
    float4 a1 = mr[lane + 32];

    float s = a0.x + a0.y + a0.z + a0.w + a1.x + a1.y + a1.z + a1.w;
    #pragma unroll
    for (int o = 16; o; o >>= 1) s += __shfl_xor_sync(0xFFFFFFFFu, s, o);
    float mu = s * (1.0f / C_M);

    float d0x = a0.x - mu, d0y = a0.y - mu, d0z = a0.z - mu, d0w = a0.w - mu;
    float d1x = a1.x - mu, d1y = a1.y - mu, d1z = a1.z - mu, d1w = a1.w - mu;
    float vs = d0x*d0x + d0y*d0y + d0z*d0z + d0w*d0w
             + d1x*d1x + d1y*d1y + d1z*d1z + d1w*d1w;
    #pragma unroll
    for (int o = 16; o; o >>= 1) vs += __shfl_xor_sync(0xFFFFFFFFu, vs, o);
    float inv = rsqrtf(vs * (1.0f / C_M) + 1e-5f);

    const float4* w4 = (const float4*)w;
    const float4* b4 = (const float4*)b;
    float4 w0 = w4[lane],  w1 = w4[lane + 32];
    float4 b0 = b4[lane],  b1 = b4[lane + 32];

    float4 o0, o1;
    o0.x = d0x * inv * w0.x + b0.x;  o0.y = d0y * inv * w0.y + b0.y;
    o0.z = d0z * inv * w0.z + b0.z;  o0.w = d0w * inv * w0.w + b0.w;
    o1.x = d1x * inv * w1.x + b1.x;  o1.y = d1y * inv * w1.y + b1.y;
    o1.z = d1z * inv * w1.z + b1.z;  o1.w = d1w * inv * w1.w + b1.w;

    float4* orow = (float4*)(out + (size_t)gwarp * C_M);
    orow[lane]      = o0;
    orow[lane + 32] = o1;
}

// ---------------------------------------------------------------------------
// z layernorm + distogram embedding, fused: one warp per (i,j) row of z.
// out[i,j,:] = LN(z[i,j,:]) + lin_b + (bin>=0 ? lin_w[:,bin] : 0)
// Persistent grid; x and transposed lin_w cached in shared.
// ---------------------------------------------------------------------------
__global__ void __launch_bounds__(256, 8)
z_fused_kernel(const float* __restrict__ z,
               const float* __restrict__ x,
               const float* __restrict__ lnw,
               const float* __restrict__ lnb,
               const float* __restrict__ linw,   // [C_Z, NUM_BINS]
               const float* __restrict__ linb,   // [C_Z]
               float* __restrict__ out) {
    __shared__ float  sh_x[N_RES * 3];                 // 12 KB
    __shared__ float4 sh_linwT[NUM_BINS * (C_Z / 4)];  // [bin][c/4], 7.5 KB
    __shared__ float4 sh_linb[C_Z / 4];

    int tid = threadIdx.x;
    for (int i = tid; i < N_RES * 3; i += blockDim.x) sh_x[i] = x[i];
    for (int i = tid; i < C_Z * NUM_BINS; i += blockDim.x) {
        int c = i / NUM_BINS, bb = i % NUM_BINS;
        ((float*)sh_linwT)[bb * C_Z + c] = linw[i];
    }
    for (int i = tid; i < C_Z; i += blockDim.x) ((float*)sh_linb)[i] = linb[i];
    __syncthreads();

    int lane = tid & 31;
    int warp = tid >> 5;

    const float4* lnw4 = (const float4*)lnw;
    const float4* lnb4 = (const float4*)lnb;
    float4 w  = lnw4[lane];
    float4 bb = lnb4[lane];
    float4 lb = sh_linb[lane];

    // squared bin edges (fp32, matching reference linspace**2)
    float sqb[NUM_BINS + 1];
    #pragma unroll
    for (int b = 0; b < NUM_BINS; b++) {
        float v = 3.25f + 1.25f * (float)b;
        sqb[b] = v * v;
    }
    sqb[NUM_BINS] = 1e8f;

    const long long total = (long long)N_RES * N_RES;
    long long gwarp  = (long long)blockIdx.x * (blockDim.x >> 5) + warp;
    long long nwarps = (long long)gridDim.x * (blockDim.x >> 5);

    for (long long r = gwarp; r < total; r += nwarps) {
        int i = (int)(r >> 10);
        int j = (int)(r & 1023);

        const float4* zr = (const float4*)(z + r * C_Z);
        float4 v = zr[lane];

        float s = v.x + v.y + v.z + v.w;
        #pragma unroll
        for (int o = 16; o; o >>= 1) s += __shfl_xor_sync(0xFFFFFFFFu, s, o);
        float mu = s * (1.0f / C_Z);

        float dx = v.x - mu, dy = v.y - mu, dz = v.z - mu, dw = v.w - mu;
        float vs = dx*dx + dy*dy + dz*dz + dw*dw;
        #pragma unroll
        for (int o = 16; o; o >>= 1) vs += __shfl_xor_sync(0xFFFFFFFFu, vs, o);
        float inv = rsqrtf(vs * (1.0f / C_Z) + 1e-5f);

        // pairwise squared distance + bin search (strict inequalities, as ref)
        float ddx = sh_x[i * 3 + 0] - sh_x[j * 3 + 0];
        float ddy = sh_x[i * 3 + 1] - sh_x[j * 3 + 1];
        float ddz = sh_x[i * 3 + 2] - sh_x[j * 3 + 2];
        float d2  = ddx * ddx + ddy * ddy + ddz * ddz;

        int bin = -1;
        #pragma unroll
        for (int b = 0; b < NUM_BINS; b++)
            if (d2 > sqb[b] && d2 < sqb[b + 1]) bin = b;

        float4 add = lb;
        if (bin >= 0) {
            float4 lw = sh_linwT[bin * (C_Z / 4) + lane];
            add.x += lw.x; add.y += lw.y; add.z += lw.z; add.w += lw.w;
        }

        float4 o4;
        o4.x = dx * inv * w.x + bb.x + add.x;
        o4.y = dy * inv * w.y + bb.y + add.y;
        o4.z = dz * inv * w.z + bb.z + add.z;
        o4.w = dw * inv * w.w + bb.w + add.w;

        ((float4*)(out + r * C_Z))[lane] = o4;
    }
}

// ---------------------------------------------------------------------------
// Inputs (metadata order): m, z, x, ln_m_w, ln_m_b, ln_z_w, ln_z_b, lin_w, lin_b
// Output: [m_update (1024*256) | z_update (1024*1024*128)] float32
// ---------------------------------------------------------------------------
extern "C" void kernel_launch(void* const* d_in, const int* in_sizes, int n_in,
                              void* d_out, int out_size) {
    const float* m      = (const float*)d_in[0];
    const float* z      = (const float*)d_in[1];
    const float* x      = (const float*)d_in[2];
    const float* ln_m_w = (const float*)d_in[3];
    const float* ln_m_b = (const float*)d_in[4];
    const float* ln_z_w = (const float*)d_in[5];
    const float* ln_z_b = (const float*)d_in[6];
    const float* lin_w  = (const float*)d_in[7];
    const float* lin_b  = (const float*)d_in[8];

    float* out_m = (float*)d_out;
    float* out_z = out_m + (size_t)N_RES * C_M;

    // m layernorm: 1024 warps -> 128 blocks x 256 threads
    m_ln_kernel<<<128, 256>>>(m, ln_m_w, ln_m_b, out_m);

    // fused z kernel: persistent grid, 8 CTAs/SM x 148 SMs
    z_fused_kernel<<<148 * 8, 256>>>(z, x, ln_z_w, ln_z_b, lin_w, lin_b, out_z);
}

// round 8
// speedup vs baseline: 1.1907x; 1.1907x over previous
#include <cuda_runtime.h>

#define N_RES 1024
#define C_M   256
#define C_Z   128
#define NUM_BINS 15

// ---------------------------------------------------------------------------
// warp sum: butterfly shuffle (sm_103a has no redux.f32)
// ---------------------------------------------------------------------------
__device__ __forceinline__ float warp_sum(float v) {
    #pragma unroll
    for (int o = 16; o; o >>= 1) v += __shfl_xor_sync(0xffffffffu, v, o);
    return v;
}

// squared bin edge t (t in [0,14]); exact vs jnp.linspace(3.25,20.75,15)**2:
// 3.25 + 1.25*t is exact in fp32, square single-rounded like the reference.
__device__ __forceinline__ float edge_sq(int t) {
    float v = fmaf(1.25f, (float)t, 3.25f);
    return v * v;
}

// Reference semantics: bin b selected iff d2 > edge²(b) && d2 < edge²(b+1)
// (strict; exact-edge equality -> no bin). sqrt gives a guess within ±1;
// adjust, then validate with the exact strict comparisons.
__device__ __forceinline__ int find_bin(float d2) {
    float s = sqrtf(d2);
    int g = __float2int_rd((s - 3.25f) * 0.8f);
    g = min(g, 14);
    if (g >= 0) {
        float lo = edge_sq(g);
        float hi = (g == 14) ? 1e8f : edge_sq(g + 1);
        if (!(d2 > lo))      g -= 1;
        else if (!(d2 < hi)) g += 1;
    }
    if (g >= 0) {
        float lo = edge_sq(g);
        float hi = (g == 14) ? 1e8f : edge_sq(g + 1);
        if (d2 > lo && d2 < hi) return g;
    }
    return -1;
}

// ---------------------------------------------------------------------------
// m layernorm: one warp per row of m [1024, 256]
// ---------------------------------------------------------------------------
__global__ void m_ln_kernel(const float* __restrict__ m,
                            const float* __restrict__ w,
                            const float* __restrict__ b,
                            float* __restrict__ out) {
    int gwarp = (blockIdx.x * blockDim.x + threadIdx.x) >> 5;
    int lane  = threadIdx.x & 31;
    if (gwarp >= N_RES) return;

    const float4* mr = (const float4*)(m + (size_t)gwarp * C_M);
    float4 a0 = mr[lane];
    float4 a1 = mr[lane + 32];

    float s = a0.x + a0.y + a0.z + a0.w + a1.x + a1.y + a1.z + a1.w;
    float q = a0.x*a0.x + a0.y*a0.y + a0.z*a0.z + a0.w*a0.w
            + a1.x*a1.x + a1.y*a1.y + a1.z*a1.z + a1.w*a1.w;
    s = warp_sum(s);
    q = warp_sum(q);
    float mu  = s * (1.0f / C_M);
    float var = fmaf(-mu, mu, q * (1.0f / C_M));
    float inv = rsqrtf(var + 1e-5f);

    const float4* w4 = (const float4*)w;
    const float4* b4 = (const float4*)b;
    float4 w0 = w4[lane],  w1 = w4[lane + 32];
    float4 b0 = b4[lane],  b1 = b4[lane + 32];

    float4 o0, o1;
    o0.x = (a0.x - mu) * inv * w0.x + b0.x;  o0.y = (a0.y - mu) * inv * w0.y + b0.y;
    o0.z = (a0.z - mu) * inv * w0.z + b0.z;  o0.w = (a0.w - mu) * inv * w0.w + b0.w;
    o1.x = (a1.x - mu) * inv * w1.x + b1.x;  o1.y = (a1.y - mu) * inv * w1.y + b1.y;
    o1.z = (a1.z - mu) * inv * w1.z + b1.z;  o1.w = (a1.w - mu) * inv * w1.w + b1.w;

    float4* orow = (float4*)(out + (size_t)gwarp * C_M);
    orow[lane]      = o0;
    orow[lane + 32] = o1;
}

// ---------------------------------------------------------------------------
// Fused z kernel: one warp per pair of consecutive rows (2p, 2p+1).
// Explicit register prefetch of the next pair hides DRAM latency.
// ---------------------------------------------------------------------------
__global__ void __launch_bounds__(256, 4)
z_fused_kernel(const float* __restrict__ z,
               const float* __restrict__ x,
               const float* __restrict__ lnw,
               const float* __restrict__ lnb,
               const float* __restrict__ linw,   // [C_Z, NUM_BINS]
               const float* __restrict__ linb,   // [C_Z]
               float* __restrict__ out) {
    __shared__ float4 sh_x4[N_RES];                      // 16 KB, xyz padded
    __shared__ float4 sh_add[(NUM_BINS + 1) * (C_Z/4)];  // [bin+1][c/4], 8 KB

    int tid = threadIdx.x;
    for (int i = tid; i < N_RES; i += blockDim.x) {
        float4 p; p.x = x[i*3+0]; p.y = x[i*3+1]; p.z = x[i*3+2]; p.w = 0.0f;
        sh_x4[i] = p;
    }
    // sh_add[0][c] = linb[c]; sh_add[b+1][c] = linb[c] + linw[c][b]
    for (int t = tid; t < (NUM_BINS + 1) * C_Z; t += blockDim.x) {
        int slot = t / C_Z, c = t % C_Z;
        float v = linb[c];
        if (slot > 0) v += linw[c * NUM_BINS + (slot - 1)];
        ((float*)sh_add)[slot * C_Z + c] = v;
    }
    __syncthreads();

    int lane = tid & 31;
    int warp = tid >> 5;

    float4 w  = ((const float4*)lnw)[lane];
    float4 bb = ((const float4*)lnb)[lane];

    const long long npairs = (long long)N_RES * N_RES / 2;
    long long gwarp  = (long long)blockIdx.x * (blockDim.x >> 5) + warp;
    long long nwarps = (long long)gridDim.x * (blockDim.x >> 5);

    long long p = gwarp;
    bool valid = (p < npairs);

    float4 a0, a1;
    if (valid) {
        const float4* base = (const float4*)(z + (p << 1) * C_Z);
        a0 = __ldcs(base + lane);
        a1 = __ldcs(base + 32 + lane);
    }

    while (valid) {
        long long pn = p + nwarps;
        bool vnext = (pn < npairs);
        float4 b0, b1;
        if (vnext) {  // prefetch next pair while computing current
            const float4* nb = (const float4*)(z + (pn << 1) * C_Z);
            b0 = __ldcs(nb + lane);
            b1 = __ldcs(nb + 32 + lane);
        }

        // ---- moments (one pass: E[x], E[x^2]) -> independent reductions ----
        float s0 = a0.x + a0.y + a0.z + a0.w;
        float q0 = a0.x*a0.x + a0.y*a0.y + a0.z*a0.z + a0.w*a0.w;
        float s1 = a1.x + a1.y + a1.z + a1.w;
        float q1 = a1.x*a1.x + a1.y*a1.y + a1.z*a1.z + a1.w*a1.w;
        s0 = warp_sum(s0); q0 = warp_sum(q0);
        s1 = warp_sum(s1); q1 = warp_sum(q1);

        float mu0  = s0 * (1.0f / C_Z);
        float var0 = fmaf(-mu0, mu0, q0 * (1.0f / C_Z));
        float inv0 = rsqrtf(var0 + 1e-5f);
        float mu1  = s1 * (1.0f / C_Z);
        float var1 = fmaf(-mu1, mu1, q1 * (1.0f / C_Z));
        float inv1 = rsqrtf(var1 + 1e-5f);

        // ---- distogram bins for rows (i, j0) and (i, j0+1) ----
        int i  = (int)(p >> 9);
        int j0 = ((int)p & 511) << 1;
        float4 xi = sh_x4[i];
        float4 xa = sh_x4[j0];
        float4 xb = sh_x4[j0 + 1];

        float dxa = xi.x - xa.x, dya = xi.y - xa.y, dza = xi.z - xa.z;
        float d2a = dxa*dxa + dya*dya + dza*dza;
        float dxb = xi.x - xb.x, dyb = xi.y - xb.y, dzb = xi.z - xb.z;
        float d2b = dxb*dxb + dyb*dyb + dzb*dzb;

        int bin0 = find_bin(d2a);
        int bin1 = find_bin(d2b);

        float4 add0 = sh_add[(bin0 + 1) * (C_Z/4) + lane];
        float4 add1 = sh_add[(bin1 + 1) * (C_Z/4) + lane];

        // ---- output: LN(z) + (lin_b [+ lin_w[:,bin]]) ----
        float4 o0, o1;
        o0.x = fmaf((a0.x - mu0) * inv0, w.x, bb.x + add0.x);
        o0.y = fmaf((a0.y - mu0) * inv0, w.y, bb.y + add0.y);
        o0.z = fmaf((a0.z - mu0) * inv0, w.z, bb.z + add0.z);
        o0.w = fmaf((a0.w - mu0) * inv0, w.w, bb.w + add0.w);
        o1.x = fmaf((a1.x - mu1) * inv1, w.x, bb.x + add1.x);
        o1.y = fmaf((a1.y - mu1) * inv1, w.y, bb.y + add1.y);
        o1.z = fmaf((a1.z - mu1) * inv1, w.z, bb.z + add1.z);
        o1.w = fmaf((a1.w - mu1) * inv1, w.w, bb.w + add1.w);

        float4* orow = (float4*)(out + (p << 1) * C_Z);
        __stcs(orow + lane, o0);
        __stcs(orow + 32 + lane, o1);

        a0 = b0; a1 = b1;
        p = pn; valid = vnext;
    }
}

// ---------------------------------------------------------------------------
// Inputs: m, z, x, ln_m_w, ln_m_b, ln_z_w, ln_z_b, lin_w, lin_b
// Output: [m_update (1024*256) | z_update (1024*1024*128)] float32
// ---------------------------------------------------------------------------
extern "C" void kernel_launch(void* const* d_in, const int* in_sizes, int n_in,
                              void* d_out, int out_size) {
    const float* m      = (const float*)d_in[0];
    const float* z      = (const float*)d_in[1];
    const float* x      = (const float*)d_in[2];
    const float* ln_m_w = (const float*)d_in[3];
    const float* ln_m_b = (const float*)d_in[4];
    const float* ln_z_w = (const float*)d_in[5];
    const float* ln_z_b = (const float*)d_in[6];
    const float* lin_w  = (const float*)d_in[7];
    const float* lin_b  = (const float*)d_in[8];

    float* out_m = (float*)d_out;
    float* out_z = out_m + (size_t)N_RES * C_M;

    m_ln_kernel<<<128, 256>>>(m, ln_m_w, ln_m_b, out_m);

    // persistent: 4 CTAs/SM x 148 SMs, 256 threads, 2 rows/warp + prefetch
    z_fused_kernel<<<148 * 4, 256>>>(z, x, ln_z_w, ln_z_b, lin_w, lin_b, out_z);
}

// round 9
// speedup vs baseline: 1.2229x; 1.0271x over previous
#include <cuda_runtime.h>

#define N_RES 1024
#define C_M   256
#define C_Z   128
#define NUM_BINS 15

// Precomputed distogram bins: g_bins[i*1024+j] = find_bin(d2(i,j)) + 1
// (0 = outside all bins -> lin_b only). 1 MB device scratch (allowed).
__device__ unsigned char g_bins[N_RES * N_RES];

// ---------------------------------------------------------------------------
// warp sum: butterfly shuffle (sm_103a has no redux.f32)
// ---------------------------------------------------------------------------
__device__ __forceinline__ float warp_sum(float v) {
    #pragma unroll
    for (int o = 16; o; o >>= 1) v += __shfl_xor_sync(0xffffffffu, v, o);
    return v;
}

// squared bin edge t (t in [0,14]); exact vs jnp.linspace(3.25,20.75,15)**2:
// 3.25 + 1.25*t is exact in fp32, square single-rounded like the reference.
__device__ __forceinline__ float edge_sq(int t) {
    float v = fmaf(1.25f, (float)t, 3.25f);
    return v * v;
}

// Reference semantics: bin b selected iff d2 > edge²(b) && d2 < edge²(b+1)
// (strict; exact-edge equality -> no bin). sqrt guess within ±1, adjust,
// then validate with the exact strict comparisons.
__device__ __forceinline__ int find_bin(float d2) {
    float s = sqrtf(d2);
    int g = __float2int_rd((s - 3.25f) * 0.8f);
    g = min(g, 14);
    if (g >= 0) {
        float lo = edge_sq(g);
        float hi = (g == 14) ? 1e8f : edge_sq(g + 1);
        if (!(d2 > lo))      g -= 1;
        else if (!(d2 < hi)) g += 1;
    }
    if (g >= 0) {
        float lo = edge_sq(g);
        float hi = (g == 14) ? 1e8f : edge_sq(g + 1);
        if (d2 > lo && d2 < hi) return g;
    }
    return -1;
}

// ---------------------------------------------------------------------------
// Prep kernel: m layernorm (first 1024 warps, one row each) + bin table
// (all threads, grid-stride over the 1M pairs).
// ---------------------------------------------------------------------------
__global__ void prep_kernel(const float* __restrict__ m,
                            const float* __restrict__ w,
                            const float* __restrict__ b,
                            const float* __restrict__ x,
                            float* __restrict__ out_m) {
    int gwarp = (blockIdx.x * blockDim.x + threadIdx.x) >> 5;
    int lane  = threadIdx.x & 31;

    // ---- m layernorm ----
    if (gwarp < N_RES) {
        const float4* mr = (const float4*)(m + (size_t)gwarp * C_M);
        float4 a0 = mr[lane];
        float4 a1 = mr[lane + 32];

        float s = a0.x + a0.y + a0.z + a0.w + a1.x + a1.y + a1.z + a1.w;
        float q = a0.x*a0.x + a0.y*a0.y + a0.z*a0.z + a0.w*a0.w
                + a1.x*a1.x + a1.y*a1.y + a1.z*a1.z + a1.w*a1.w;
        s = warp_sum(s);
        q = warp_sum(q);
        float mu  = s * (1.0f / C_M);
        float var = fmaf(-mu, mu, q * (1.0f / C_M));
        float inv = rsqrtf(var + 1e-5f);

        const float4* w4 = (const float4*)w;
        const float4* b4 = (const float4*)b;
        float4 w0 = w4[lane],  w1 = w4[lane + 32];
        float4 b0 = b4[lane],  b1 = b4[lane + 32];

        float4 o0, o1;
        o0.x = (a0.x - mu) * inv * w0.x + b0.x;  o0.y = (a0.y - mu) * inv * w0.y + b0.y;
        o0.z = (a0.z - mu) * inv * w0.z + b0.z;  o0.w = (a0.w - mu) * inv * w0.w + b0.w;
        o1.x = (a1.x - mu) * inv * w1.x + b1.x;  o1.y = (a1.y - mu) * inv * w1.y + b1.y;
        o1.z = (a1.z - mu) * inv * w1.z + b1.z;  o1.w = (a1.w - mu) * inv * w1.w + b1.w;

        float4* orow = (float4*)(out_m + (size_t)gwarp * C_M);
        orow[lane]      = o0;
        orow[lane + 32] = o1;
    }

    // ---- bin table: one byte per (i,j) pair ----
    int t      = blockIdx.x * blockDim.x + threadIdx.x;
    int stride = gridDim.x * blockDim.x;
    for (int p = t; p < N_RES * N_RES; p += stride) {
        int i = p >> 10;
        int j = p & 1023;
        float dx = __ldg(x + i*3 + 0) - __ldg(x + j*3 + 0);
        float dy = __ldg(x + i*3 + 1) - __ldg(x + j*3 + 1);
        float dz = __ldg(x + i*3 + 2) - __ldg(x + j*3 + 2);
        float d2 = dx*dx + dy*dy + dz*dz;
        g_bins[p] = (unsigned char)(find_bin(d2) + 1);
    }
}

// ---------------------------------------------------------------------------
// Fused z kernel: one warp per pair of consecutive rows (2p, 2p+1).
// Bin lookup is a single broadcast 2-byte load from the precomputed table.
// ---------------------------------------------------------------------------
__global__ void __launch_bounds__(256, 4)
z_fused_kernel(const float* __restrict__ z,
               const float* __restrict__ lnw,
               const float* __restrict__ lnb,
               const float* __restrict__ linw,   // [C_Z, NUM_BINS]
               const float* __restrict__ linb,   // [C_Z]
               float* __restrict__ out) {
    __shared__ float4 sh_add[(NUM_BINS + 1) * (C_Z/4)];  // [slot][c/4], 8 KB

    int tid = threadIdx.x;
    // sh_add[0][c] = linb[c]; sh_add[b+1][c] = linb[c] + linw[c][b]
    for (int t = tid; t < (NUM_BINS + 1) * C_Z; t += blockDim.x) {
        int slot = t / C_Z, c = t % C_Z;
        float v = linb[c];
        if (slot > 0) v += linw[c * NUM_BINS + (slot - 1)];
        ((float*)sh_add)[slot * C_Z + c] = v;
    }
    __syncthreads();

    int lane = tid & 31;
    int warp = tid >> 5;

    float4 w  = ((const float4*)lnw)[lane];
    float4 bb = ((const float4*)lnb)[lane];

    const int npairs = N_RES * N_RES / 2;
    int gwarp  = blockIdx.x * (blockDim.x >> 5) + warp;
    int nwarps = gridDim.x * (blockDim.x >> 5);

    int p = gwarp;
    bool valid = (p < npairs);

    float4 a0, a1;
    unsigned int bins;
    if (valid) {
        const float4* base = (const float4*)(z + ((size_t)p << 8));
        a0 = __ldcs(base + lane);
        a1 = __ldcs(base + 32 + lane);
        bins = *(const unsigned short*)(g_bins + ((size_t)p << 1));
    }

    while (valid) {
        int pn = p + nwarps;
        bool vnext = (pn < npairs);
        float4 b0, b1;
        unsigned int binsn = 0;
        if (vnext) {  // prefetch next pair while computing current
            const float4* nb = (const float4*)(z + ((size_t)pn << 8));
            b0 = __ldcs(nb + lane);
            b1 = __ldcs(nb + 32 + lane);
            binsn = *(const unsigned short*)(g_bins + ((size_t)pn << 1));
        }

        // ---- moments (E[x], E[x^2]) -> 4 independent reductions ----
        float s0 = a0.x + a0.y + a0.z + a0.w;
        float q0 = a0.x*a0.x + a0.y*a0.y + a0.z*a0.z + a0.w*a0.w;
        float s1 = a1.x + a1.y + a1.z + a1.w;
        float q1 = a1.x*a1.x + a1.y*a1.y + a1.z*a1.z + a1.w*a1.w;
        s0 = warp_sum(s0); q0 = warp_sum(q0);
        s1 = warp_sum(s1); q1 = warp_sum(q1);

        float mu0  = s0 * (1.0f / C_Z);
        float var0 = fmaf(-mu0, mu0, q0 * (1.0f / C_Z));
        float inv0 = rsqrtf(var0 + 1e-5f);
        float mu1  = s1 * (1.0f / C_Z);
        float var1 = fmaf(-mu1, mu1, q1 * (1.0f / C_Z));
        float inv1 = rsqrtf(var1 + 1e-5f);

        // ---- distogram add vectors via precomputed bin slots ----
        int slot0 = (int)(bins & 0xFFu);
        int slot1 = (int)(bins >> 8);
        float4 add0 = sh_add[slot0 * (C_Z/4) + lane];
        float4 add1 = sh_add[slot1 * (C_Z/4) + lane];

        // ---- output: LN(z) + (lin_b [+ lin_w[:,bin]]) ----
        float4 o0, o1;
        o0.x = fmaf((a0.x - mu0) * inv0, w.x, bb.x + add0.x);
        o0.y = fmaf((a0.y - mu0) * inv0, w.y, bb.y + add0.y);
        o0.z = fmaf((a0.z - mu0) * inv0, w.z, bb.z + add0.z);
        o0.w = fmaf((a0.w - mu0) * inv0, w.w, bb.w + add0.w);
        o1.x = fmaf((a1.x - mu1) * inv1, w.x, bb.x + add1.x);
        o1.y = fmaf((a1.y - mu1) * inv1, w.y, bb.y + add1.y);
        o1.z = fmaf((a1.z - mu1) * inv1, w.z, bb.z + add1.z);
        o1.w = fmaf((a1.w - mu1) * inv1, w.w, bb.w + add1.w);

        float4* orow = (float4*)(out + ((size_t)p << 8));
        __stcs(orow + lane, o0);
        __stcs(orow + 32 + lane, o1);

        a0 = b0; a1 = b1; bins = binsn;
        p = pn; valid = vnext;
    }
}

// ---------------------------------------------------------------------------
// Inputs: m, z, x, ln_m_w, ln_m_b, ln_z_w, ln_z_b, lin_w, lin_b
// Output: [m_update (1024*256) | z_update (1024*1024*128)] float32
// ---------------------------------------------------------------------------
extern "C" void kernel_launch(void* const* d_in, const int* in_sizes, int n_in,
                              void* d_out, int out_size) {
    const float* m      = (const float*)d_in[0];
    const float* z      = (const float*)d_in[1];
    const float* x      = (const float*)d_in[2];
    const float* ln_m_w = (const float*)d_in[3];
    const float* ln_m_b = (const float*)d_in[4];
    const float* ln_z_w = (const float*)d_in[5];
    const float* ln_z_b = (const float*)d_in[6];
    const float* lin_w  = (const float*)d_in[7];
    const float* lin_b  = (const float*)d_in[8];

    float* out_m = (float*)d_out;
    float* out_z = out_m + (size_t)N_RES * C_M;

    // Prep: m layernorm + distogram bin table (one full-chip wave)
    prep_kernel<<<1184, 256>>>(m, ln_m_w, ln_m_b, x, out_m);

    // Fused z: persistent 4 CTAs/SM x 148 SMs, 2 rows/warp + prefetch
    z_fused_kernel<<<148 * 4, 256>>>(z, ln_z_w, ln_z_b, lin_w, lin_b, out_z);
}

// round 10
// speedup vs baseline: 1.2337x; 1.0088x over previous
#include <cuda_runtime.h>

#define N_RES 1024
#define C_M   256
#define C_Z   128
#define NUM_BINS 15

#define GRID_CTAS   592          // 4 per SM x 148
#define WARPS_CTA   8
#define NWARPS      (GRID_CTAS * WARPS_CTA)          // 4736
#define NPAIRS      (N_RES * N_RES / 2)              // 524288
#define K_MAX       ((NPAIRS + NWARPS - 1) / NWARPS) // 111

// ---------------------------------------------------------------------------
// warp sum: butterfly shuffle (sm_103a has no redux.f32)
// ---------------------------------------------------------------------------
__device__ __forceinline__ float warp_sum(float v) {
    #pragma unroll
    for (int o = 16; o; o >>= 1) v += __shfl_xor_sync(0xffffffffu, v, o);
    return v;
}

// squared bin edge t (t in [0,14]); exact vs jnp.linspace(3.25,20.75,15)**2:
// 3.25 + 1.25*t is exact in fp32, square single-rounded like the reference.
__device__ __forceinline__ float edge_sq(int t) {
    float v = fmaf(1.25f, (float)t, 3.25f);
    return v * v;
}

// Reference semantics: bin b selected iff d2 > edge²(b) && d2 < edge²(b+1)
// (strict; exact-edge equality -> no bin). sqrt guess within ±1, adjust,
// then validate with the exact strict comparisons.
__device__ __forceinline__ int find_bin(float d2) {
    float s = sqrtf(d2);
    int g = __float2int_rd((s - 3.25f) * 0.8f);
    g = min(g, 14);
    if (g >= 0) {
        float lo = edge_sq(g);
        float hi = (g == 14) ? 1e8f : edge_sq(g + 1);
        if (!(d2 > lo))      g -= 1;
        else if (!(d2 < hi)) g += 1;
    }
    if (g >= 0) {
        float lo = edge_sq(g);
        float hi = (g == 14) ? 1e8f : edge_sq(g + 1);
        if (d2 > lo && d2 < hi) return g;
    }
    return -1;
}

// ---------------------------------------------------------------------------
// ONE kernel: prologue does (a) m layernorm on the first 1024 warps,
// (b) per-warp distogram bin precompute into smem; main loop streams z.
// ---------------------------------------------------------------------------
__global__ void __launch_bounds__(256, 4)
fused_kernel(const float* __restrict__ m,
             const float* __restrict__ ln_m_w,
             const float* __restrict__ ln_m_b,
             const float* __restrict__ z,
             const float* __restrict__ x,
             const float* __restrict__ lnw,
             const float* __restrict__ lnb,
             const float* __restrict__ linw,   // [C_Z, NUM_BINS]
             const float* __restrict__ linb,   // [C_Z]
             float* __restrict__ out_m,
             float* __restrict__ out_z) {
    __shared__ float4 sh_add[(NUM_BINS + 1) * (C_Z/4)];       // 8 KB
    __shared__ unsigned short sh_bins[WARPS_CTA][K_MAX + 1];  // ~1.8 KB

    int tid  = threadIdx.x;
    int lane = tid & 31;
    int warp = tid >> 5;
    int gwarp = blockIdx.x * WARPS_CTA + warp;

    // ---- build add table: sh_add[0]=linb; sh_add[b+1]=linb+linw[:,b] ----
    for (int t = tid; t < (NUM_BINS + 1) * C_Z; t += blockDim.x) {
        int slot = t / C_Z, c = t % C_Z;
        float v = linb[c];
        if (slot > 0) v += linw[c * NUM_BINS + (slot - 1)];
        ((float*)sh_add)[slot * C_Z + c] = v;
    }

    // ---- m layernorm: first 1024 warps, one row each ----
    if (gwarp < N_RES) {
        const float4* mr = (const float4*)(m + (size_t)gwarp * C_M);
        float4 a0 = mr[lane];
        float4 a1 = mr[lane + 32];

        float s = a0.x + a0.y + a0.z + a0.w + a1.x + a1.y + a1.z + a1.w;
        float q = a0.x*a0.x + a0.y*a0.y + a0.z*a0.z + a0.w*a0.w
                + a1.x*a1.x + a1.y*a1.y + a1.z*a1.z + a1.w*a1.w;
        s = warp_sum(s);
        q = warp_sum(q);
        float mu  = s * (1.0f / C_M);
        float var = fmaf(-mu, mu, q * (1.0f / C_M));
        float inv = rsqrtf(var + 1e-5f);

        float4 w0 = ((const float4*)ln_m_w)[lane];
        float4 w1 = ((const float4*)ln_m_w)[lane + 32];
        float4 b0 = ((const float4*)ln_m_b)[lane];
        float4 b1 = ((const float4*)ln_m_b)[lane + 32];

        float4 o0, o1;
        o0.x = (a0.x - mu) * inv * w0.x + b0.x;  o0.y = (a0.y - mu) * inv * w0.y + b0.y;
        o0.z = (a0.z - mu) * inv * w0.z + b0.z;  o0.w = (a0.w - mu) * inv * w0.w + b0.w;
        o1.x = (a1.x - mu) * inv * w1.x + b1.x;  o1.y = (a1.y - mu) * inv * w1.y + b1.y;
        o1.z = (a1.z - mu) * inv * w1.z + b1.z;  o1.w = (a1.w - mu) * inv * w1.w + b1.w;

        float4* orow = (float4*)(out_m + (size_t)gwarp * C_M);
        orow[lane]      = o0;
        orow[lane + 32] = o1;
    }

    // ---- per-warp bin precompute: this warp's pairs are gwarp + k*NWARPS ----
    int iters = (gwarp < NPAIRS) ? ((NPAIRS - 1 - gwarp) / NWARPS + 1) : 0;
    for (int k = lane; k < iters; k += 32) {
        int p  = gwarp + k * NWARPS;
        int i  = p >> 9;
        int j0 = (p & 511) << 1;
        float xi0 = __ldg(x + i*3 + 0), xi1 = __ldg(x + i*3 + 1), xi2 = __ldg(x + i*3 + 2);
        float dxa = xi0 - __ldg(x + j0*3 + 0);
        float dya = xi1 - __ldg(x + j0*3 + 1);
        float dza = xi2 - __ldg(x + j0*3 + 2);
        float dxb = xi0 - __ldg(x + j0*3 + 3);
        float dyb = xi1 - __ldg(x + j0*3 + 4);
        float dzb = xi2 - __ldg(x + j0*3 + 5);
        float d2a = dxa*dxa + dya*dya + dza*dza;
        float d2b = dxb*dxb + dyb*dyb + dzb*dzb;
        int s0 = find_bin(d2a) + 1;
        int s1 = find_bin(d2b) + 1;
        sh_bins[warp][k] = (unsigned short)(s0 | (s1 << 8));
    }
    __syncwarp();
    __syncthreads();   // sh_add ready for all warps

    // ---- main streaming loop: 2 z rows per iteration + register prefetch ----
    float4 w  = ((const float4*)lnw)[lane];
    float4 bb = ((const float4*)lnb)[lane];

    if (iters == 0) return;

    const float4* zp = (const float4*)(z     + ((size_t)gwarp << 8));
    float4*       op = (float4*)      (out_z + ((size_t)gwarp << 8));
    const size_t step = (size_t)NWARPS << 6;   // NWARPS*256 floats / 4

    float4 a0 = __ldcs(zp + lane);
    float4 a1 = __ldcs(zp + 32 + lane);

    for (int k = 0; k < iters; k++) {
        float4 b0, b1;
        if (k + 1 < iters) {   // prefetch next pair of rows
            const float4* nb = zp + step;
            b0 = __ldcs(nb + lane);
            b1 = __ldcs(nb + 32 + lane);
        }

        // moments (E[x], E[x^2]) -> 4 independent reductions
        float s0 = a0.x + a0.y + a0.z + a0.w;
        float q0 = a0.x*a0.x + a0.y*a0.y + a0.z*a0.z + a0.w*a0.w;
        float s1 = a1.x + a1.y + a1.z + a1.w;
        float q1 = a1.x*a1.x + a1.y*a1.y + a1.z*a1.z + a1.w*a1.w;
        s0 = warp_sum(s0); q0 = warp_sum(q0);
        s1 = warp_sum(s1); q1 = warp_sum(q1);

        float mu0  = s0 * (1.0f / C_Z);
        float var0 = fmaf(-mu0, mu0, q0 * (1.0f / C_Z));
        float inv0 = rsqrtf(var0 + 1e-5f);
        float mu1  = s1 * (1.0f / C_Z);
        float var1 = fmaf(-mu1, mu1, q1 * (1.0f / C_Z));
        float inv1 = rsqrtf(var1 + 1e-5f);

        // distogram add vectors via per-warp smem bin slots (broadcast LDS)
        unsigned int bins = sh_bins[warp][k];
        float4 add0 = sh_add[(bins & 0xFFu) * (C_Z/4) + lane];
        float4 add1 = sh_add[(bins >> 8)   * (C_Z/4) + lane];

        float4 o0, o1;
        o0.x = fmaf((a0.x - mu0) * inv0, w.x, bb.x + add0.x);
        o0.y = fmaf((a0.y - mu0) * inv0, w.y, bb.y + add0.y);
        o0.z = fmaf((a0.z - mu0) * inv0, w.z, bb.z + add0.z);
        o0.w = fmaf((a0.w - mu0) * inv0, w.w, bb.w + add0.w);
        o1.x = fmaf((a1.x - mu1) * inv1, w.x, bb.x + add1.x);
        o1.y = fmaf((a1.y - mu1) * inv1, w.y, bb.y + add1.y);
        o1.z = fmaf((a1.z - mu1) * inv1, w.z, bb.z + add1.z);
        o1.w = fmaf((a1.w - mu1) * inv1, w.w, bb.w + add1.w);

        __stcs(op + lane, o0);
        __stcs(op + 32 + lane, o1);

        a0 = b0; a1 = b1;
        zp += step; op += step;
    }
}

// ---------------------------------------------------------------------------
// Inputs: m, z, x, ln_m_w, ln_m_b, ln_z_w, ln_z_b, lin_w, lin_b
// Output: [m_update (1024*256) | z_update (1024*1024*128)] float32
// ---------------------------------------------------------------------------
extern "C" void kernel_launch(void* const* d_in, const int* in_sizes, int n_in,
                              void* d_out, int out_size) {
    const float* m      = (const float*)d_in[0];
    const float* z      = (const float*)d_in[1];
    const float* x      = (const float*)d_in[2];
    const float* ln_m_w = (const float*)d_in[3];
    const float* ln_m_b = (const float*)d_in[4];
    const float* ln_z_w = (const float*)d_in[5];
    const float* ln_z_b = (const float*)d_in[6];
    const float* lin_w  = (const float*)d_in[7];
    const float* lin_b  = (const float*)d_in[8];

    float* out_m = (float*)d_out;
    float* out_z = out_m + (size_t)N_RES * C_M;

    fused_kernel<<<GRID_CTAS, 256>>>(m, ln_m_w, ln_m_b, z, x,
                                     ln_z_w, ln_z_b, lin_w, lin_b,
                                     out_m, out_z);
}